// round 10
// baseline (speedup 1.0000x reference)
#include <cuda_runtime.h>
#include <cuda_bf16.h>
#include <cstdint>
#include <math.h>

#define TT 256
#define BB 32
#define HH 256
#define KK 48
#define GATES 1024          // 4*H
#define ROWS_TB (TT*BB)     // 8192

// ---------------- device scratch (no allocations allowed) ----------------
__device__ float g_x0[ROWS_TB * 256];        // embedded input (t,b,e)
__device__ float g_gxf[ROWS_TB * GATES];     // x@Wih^T + b, fwd
__device__ float g_gxb[ROWS_TB * GATES];     // x@Wih^T + b, bwd
__device__ float g_h1[ROWS_TB * 512];        // layer-0 output (hf|hb)
__device__ float g_h2[ROWS_TB * 512];        // layer-1 output
__device__ float g_emit[ROWS_TB * KK];       // emissions (t,b,k)
__device__ float g_scr[BB];                  // per-batch (num-den)

// L2-exchange: h[par][dir][bg16][2*256], flags [dir][bg16][rank8]
__device__ float g_hx[2 * 2 * 16 * 512];     // 32768 floats
__device__ int   g_flag[2 * 16 * 8];         // 256 ints

// output layout: [emit (B,T,K) fp32 | loss | mask (B,T)]
#define EMIT_N   (BB*TT*KK)      // 393216
#define LOSS_OFF EMIT_N
#define MASK_OFF (EMIT_N + 1)

// ---------------- helpers ----------------
__device__ __forceinline__ float sigf(float x) { return 1.0f / (1.0f + __expf(-x)); }

__device__ __forceinline__ uint32_t smem_u32(const void* p) {
    uint32_t a;
    asm("{ .reg .u64 t; cvta.to.shared.u64 t, %1; cvt.u32.u64 %0, t; }" : "=r"(a) : "l"(p));
    return a;
}
// pack (lo half = a, hi half = b) into bf16x2
__device__ __forceinline__ uint32_t pk2(float a, float b) {
    uint32_t r;
    asm("cvt.rn.bf16x2.f32 %0, %1, %2;" : "=r"(r) : "f"(b), "f"(a));
    return r;
}
__device__ __forceinline__ void ldm_x4(uint32_t* r, uint32_t addr) {
    asm volatile("ldmatrix.sync.aligned.m8n8.x4.shared.b16 {%0,%1,%2,%3}, [%4];"
                 : "=r"(r[0]), "=r"(r[1]), "=r"(r[2]), "=r"(r[3]) : "r"(addr));
}
__device__ __forceinline__ void ldm_x2(uint32_t* r, uint32_t addr) {
    asm volatile("ldmatrix.sync.aligned.m8n8.x2.shared.b16 {%0,%1}, [%2];"
                 : "=r"(r[0]), "=r"(r[1]) : "r"(addr));
}
__device__ __forceinline__ void mma16816(float* c, const uint32_t* a, const uint32_t* b) {
    asm volatile("mma.sync.aligned.m16n8k16.row.col.f32.bf16.bf16.f32 "
                 "{%0,%1,%2,%3}, {%4,%5,%6,%7}, {%8,%9}, {%0,%1,%2,%3};"
                 : "+f"(c[0]), "+f"(c[1]), "+f"(c[2]), "+f"(c[3])
                 : "r"(a[0]), "r"(a[1]), "r"(a[2]), "r"(a[3]), "r"(b[0]), "r"(b[1]));
}
__device__ __forceinline__ int ld_acq(const int* p) {
    int v;
    asm volatile("ld.acquire.gpu.global.s32 %0, [%1];" : "=r"(v) : "l"(p) : "memory");
    return v;
}
__device__ __forceinline__ void st_rel(int* p, int v) {
    asm volatile("st.relaxed.gpu.global.s32 [%0], %1;" :: "l"(p), "r"(v) : "memory");
}

// ---------------- embedding gather ----------------
__global__ void embed_kernel(const int* __restrict__ sent,
                             const float* __restrict__ embed,
                             float* __restrict__ x0) {
    int bid = blockIdx.x;            // t*32 + b
    int t = bid >> 5, b = bid & 31;
    int tok = sent[b * TT + t];
    x0[(size_t)bid * 256 + threadIdx.x] = embed[(size_t)tok * 256 + threadIdx.x];
}

// ---------------- mma.sync bf16x3 GEMM: C[M,N] = A[M,K] * W[N,K]^T + bias ----------------
#define MG_AHI 0
#define MG_ALO 18432
#define MG_BHI 36864
#define MG_BLO 46080
#define MG_TOTAL 55296
#define APITCH 72

__global__ void __launch_bounds__(256)
mma_gemm(const float* __restrict__ A,
         const float* __restrict__ Wf, const float* __restrict__ Wb,
         const float* __restrict__ biasf, const float* __restrict__ biasb,
         float* __restrict__ Cf, float* __restrict__ Cb,
         int K, int Nout) {
    extern __shared__ char smc[];
    uint32_t sb = smem_u32(smc);
    int tid = threadIdx.x, wid = tid >> 5, l = tid & 31;
    int m0 = blockIdx.y * 128, n0 = blockIdx.x * 64;
    const float* W    = blockIdx.z ? Wb : Wf;
    const float* bias = blockIdx.z ? biasb : biasf;
    float*       C    = blockIdx.z ? Cb : Cf;

    int wm = wid & 3, wn = wid >> 2;
    int srow = tid >> 4;
    int scol = (tid & 15) << 2;

    float c[2][4][4];
#pragma unroll
    for (int mi = 0; mi < 2; mi++)
#pragma unroll
        for (int ni = 0; ni < 4; ni++)
#pragma unroll
            for (int j = 0; j < 4; j++) c[mi][ni][j] = 0.0f;

    int nch = K >> 6;
    for (int ch = 0; ch < nch; ch++) {
        int kc = ch << 6;
#pragma unroll
        for (int rr = 0; rr < 8; rr++) {
            int row = srow + rr * 16;
            float4 v = *(const float4*)&A[(size_t)(m0 + row) * K + kc + scol];
            float hx = __bfloat162float(__float2bfloat16(v.x));
            float hy = __bfloat162float(__float2bfloat16(v.y));
            float hz = __bfloat162float(__float2bfloat16(v.z));
            float hw = __bfloat162float(__float2bfloat16(v.w));
            uint32_t off = (uint32_t)(row * APITCH + scol) * 2;
            *(uint2*)(smc + MG_AHI + off) = make_uint2(pk2(hx, hy), pk2(hz, hw));
            *(uint2*)(smc + MG_ALO + off) =
                make_uint2(pk2(v.x - hx, v.y - hy), pk2(v.z - hz, v.w - hw));
        }
#pragma unroll
        for (int rr = 0; rr < 4; rr++) {
            int row = srow + rr * 16;
            int n = n0 + row;
            float4 v = make_float4(0.f, 0.f, 0.f, 0.f);
            if (n < Nout) v = *(const float4*)&W[(size_t)n * K + kc + scol];
            float hx = __bfloat162float(__float2bfloat16(v.x));
            float hy = __bfloat162float(__float2bfloat16(v.y));
            float hz = __bfloat162float(__float2bfloat16(v.z));
            float hw = __bfloat162float(__float2bfloat16(v.w));
            uint32_t off = (uint32_t)(row * APITCH + scol) * 2;
            *(uint2*)(smc + MG_BHI + off) = make_uint2(pk2(hx, hy), pk2(hz, hw));
            *(uint2*)(smc + MG_BLO + off) =
                make_uint2(pk2(v.x - hx, v.y - hy), pk2(v.z - hz, v.w - hw));
        }
        __syncthreads();

#pragma unroll
        for (int ks = 0; ks < 4; ks++) {
            uint32_t ah[2][4], al[2][4];
#pragma unroll
            for (int mi = 0; mi < 2; mi++) {
                uint32_t off =
                    (uint32_t)((wm * 32 + mi * 16 + (l & 15)) * APITCH +
                               ks * 16 + (l >> 4) * 8) * 2;
                ldm_x4(ah[mi], sb + MG_AHI + off);
                ldm_x4(al[mi], sb + MG_ALO + off);
            }
            uint32_t bh[4][2], bl[4][2];
#pragma unroll
            for (int ni = 0; ni < 4; ni++) {
                uint32_t off =
                    (uint32_t)((wn * 32 + ni * 8 + (l & 7)) * APITCH +
                               ks * 16 + ((l >> 3) & 1) * 8) * 2;
                ldm_x2(bh[ni], sb + MG_BHI + off);
                ldm_x2(bl[ni], sb + MG_BLO + off);
            }
#pragma unroll
            for (int mi = 0; mi < 2; mi++)
#pragma unroll
                for (int ni = 0; ni < 4; ni++) {
                    mma16816(c[mi][ni], ah[mi], bh[ni]);
                    mma16816(c[mi][ni], al[mi], bh[ni]);
                    mma16816(c[mi][ni], ah[mi], bl[ni]);
                }
        }
        __syncthreads();
    }

#pragma unroll
    for (int mi = 0; mi < 2; mi++) {
#pragma unroll
        for (int ni = 0; ni < 4; ni++) {
#pragma unroll
            for (int j = 0; j < 4; j++) {
                int row = m0 + wm * 32 + mi * 16 + (l >> 2) + (j >> 1) * 8;
                int col = n0 + wn * 32 + ni * 8 + (l & 3) * 2 + (j & 1);
                if (col < Nout)
                    C[(size_t)row * Nout + col] = c[mi][ni][j] + bias[col];
            }
        }
    }
}

// ---------------- reset for the L2-exchange state ----------------
__global__ void lstm_reset() {
    int idx = blockIdx.x * blockDim.x + threadIdx.x;
    if (idx < 2 * 2 * 16 * 512) g_hx[idx] = 0.0f;
    if (idx < 2 * 16 * 8) g_flag[idx] = 0;
}

// ---------------- BiLSTM layer v6: dual-direction interleave, L2 flag exchange ----
// 128 CTAs = 8 ranks x 16 batch-groups (2 batches each). Each CTA advances BOTH
// directions; the exchange latency of one direction hides behind the other's
// compute. Whh_fwd slice in SMEM (fp32 transposed), Whh_bwd slice in REGISTERS
// (128 floats/thread, fully unrolled). Single-fence flag publication.
#define WPITCH 132
#define OFF_WHHT 0
#define OFF_HBUF (256 * WPITCH)                  // 33792 floats; [dir][par][512]
#define OFF_RED  (OFF_HBUF + 2048)               // 35840; [g*2+b]
#define OFF_GSM  (OFF_RED + 256)                 // 36096; [(b*4+q)*32+u]
#define LSTM_SMEM_FLOATS (OFF_GSM + 256)         // 36352
#define LSTM_SMEM_BYTES  (LSTM_SMEM_FLOATS * 4)  // 145408

__global__ void __launch_bounds__(256, 1)
lstm_layer(const float* __restrict__ GxF, const float* __restrict__ GxB,
           const float* __restrict__ WhhF, const float* __restrict__ WhhB,
           const int* __restrict__ lengths, float* __restrict__ Hout) {
    extern __shared__ float sm[];
    float* WhhT = sm + OFF_WHHT;
    float* hbuf = sm + OFF_HBUF;
    float* red  = sm + OFF_RED;
    float* gsm  = sm + OFF_GSM;

    int tid = threadIdx.x;
    int l   = tid & 31;
    int r   = blockIdx.x & 7;
    int bg  = blockIdx.x >> 3;           // 0..15, 2 batches each
    int batch0 = bg * 2;

    int g128 = tid & 127;
    int kh   = tid >> 7;
    int kbase = kh << 7;
    int grow = ((g128 >> 5) << 8) + (r << 5) + (g128 & 31);

    // stage fwd Whh slice transposed (fp32): WhhT[k][g]
    for (int idx = tid; idx < 128 * 256; idx += 256) {
        int g = idx >> 8;
        int k = idx & 255;
        int q = g >> 5, u = g & 31;
        WhhT[k * WPITCH + g] = WhhF[(size_t)((q << 8) + (r << 5) + u) * 256 + k];
    }

    // bwd Whh slice into registers: wb[i] = WhhB[grow][kbase+i]
    float wb[128];
    {
        const float4* wrow = (const float4*)(WhhB + (size_t)grow * 256 + kbase);
#pragma unroll
        for (int i = 0; i < 32; i++) {
            float4 v = wrow[i];
            wb[4 * i + 0] = v.x; wb[4 * i + 1] = v.y;
            wb[4 * i + 2] = v.z; wb[4 * i + 3] = v.w;
        }
    }
    __syncthreads();

    int* flgF = g_flag + (0 * 16 + bg) * 8;
    int* flgB = g_flag + (1 * 16 + bg) * 8;

    int b2 = tid >> 5, uu = tid & 31;    // producer mapping (tid<64)
    int mylen = 0;
    if (tid < 64) mylen = lengths[batch0 + b2];
    float cF = 0.f, hF = 0.f, cB = 0.f, hB = 0.f;

    for (int s = 0; s < TT; ++s) {
        int tf = s;
        int tb = TT - 1 - s;
        int par = s & 1, nxt = par ^ 1;
        bool last = (s == TT - 1);

        // prefetch gate-x for both dirs (kh==0 threads own gate grow, 2 batches)
        float gfa = 0.f, gfb = 0.f, gba = 0.f, gbb = 0.f;
        if (kh == 0) {
            const float* gpf = GxF + ((size_t)tf * BB + batch0) * GATES + grow;
            gfa = gpf[0]; gfb = gpf[GATES];
            const float* gpb = GxB + ((size_t)tb * BB + batch0) * GATES + grow;
            gba = gpb[0]; gbb = gpb[GATES];
        }

        // ================= FWD phase =================
        if (s > 0) {
            for (;;) {
                bool ok = (l < 8) ? (ld_acq(flgF + l) >= s) : true;
                if (__all_sync(0xffffffffu, ok)) break;
            }
        }
        if (tid < 128) {
            const float4* src = (const float4*)(g_hx + ((par * 2 + 0) * 16 + bg) * 512);
            float4 v = __ldcg(src + tid);
            *(float4*)&hbuf[(0 * 2 + par) * 512 + tid * 4] = v;
        }
        __syncthreads();

        {
            const float* hb0 = hbuf + (0 * 2 + par) * 512 + kbase;
            const float* hb1 = hb0 + 256;
            const float* wp  = WhhT + kbase * WPITCH + g128;
            float a0 = 0.f, a1 = 0.f;
#pragma unroll 8
            for (int k = 0; k < 128; k += 4) {
                float4 h0 = *(const float4*)(hb0 + k);
                float4 h1 = *(const float4*)(hb1 + k);
                float w0 = wp[(k + 0) * WPITCH];
                float w1 = wp[(k + 1) * WPITCH];
                float w2 = wp[(k + 2) * WPITCH];
                float w3 = wp[(k + 3) * WPITCH];
                a0 += w0 * h0.x; a0 += w1 * h0.y; a0 += w2 * h0.z; a0 += w3 * h0.w;
                a1 += w0 * h1.x; a1 += w1 * h1.y; a1 += w2 * h1.z; a1 += w3 * h1.w;
            }
            if (kh) { red[g128 * 2 + 0] = a0; red[g128 * 2 + 1] = a1; }
            __syncthreads();
            if (!kh) {
                int q = g128 >> 5, u = g128 & 31;
                gsm[(0 * 4 + q) * 32 + u] = a0 + red[g128 * 2 + 0] + gfa;
                gsm[(1 * 4 + q) * 32 + u] = a1 + red[g128 * 2 + 1] + gfb;
            }
            __syncthreads();
        }

        if (tid < 64) {
            float iv = gsm[(b2 * 4 + 0) * 32 + uu];
            float fv = gsm[(b2 * 4 + 1) * 32 + uu];
            float gv = gsm[(b2 * 4 + 2) * 32 + uu];
            float ov = gsm[(b2 * 4 + 3) * 32 + uu];
            float c2 = sigf(fv) * cF + sigf(iv) * tanhf(gv);
            float h2 = sigf(ov) * tanhf(c2);
            bool m = (tf < mylen);
            float hn = m ? h2 : hF;
            cF = m ? c2 : cF;
            hF = hn;
            if (!last)
                g_hx[((nxt * 2 + 0) * 16 + bg) * 512 + (b2 << 8) + (r << 5) + uu] = hn;
            Hout[((size_t)tf * BB + batch0 + b2) * 512 + 0 * 256 + (r << 5) + uu] =
                m ? h2 : 0.0f;
        }
        __syncthreads();
        if (!last && tid == 0) { __threadfence(); st_rel(flgF + r, s + 1); }

        // ================= BWD phase =================
        if (s > 0) {
            for (;;) {
                bool ok = (l < 8) ? (ld_acq(flgB + l) >= s) : true;
                if (__all_sync(0xffffffffu, ok)) break;
            }
        }
        if (tid < 128) {
            const float4* src = (const float4*)(g_hx + ((par * 2 + 1) * 16 + bg) * 512);
            float4 v = __ldcg(src + tid);
            *(float4*)&hbuf[(1 * 2 + par) * 512 + tid * 4] = v;
        }
        __syncthreads();

        {
            const float* hb0 = hbuf + (1 * 2 + par) * 512 + kbase;
            const float* hb1 = hb0 + 256;
            float a0 = 0.f, a1 = 0.f;
#pragma unroll
            for (int kb = 0; kb < 32; kb++) {
                float4 h0 = *(const float4*)(hb0 + 4 * kb);
                float4 h1 = *(const float4*)(hb1 + 4 * kb);
                a0 += wb[4 * kb + 0] * h0.x; a0 += wb[4 * kb + 1] * h0.y;
                a0 += wb[4 * kb + 2] * h0.z; a0 += wb[4 * kb + 3] * h0.w;
                a1 += wb[4 * kb + 0] * h1.x; a1 += wb[4 * kb + 1] * h1.y;
                a1 += wb[4 * kb + 2] * h1.z; a1 += wb[4 * kb + 3] * h1.w;
            }
            if (kh) { red[g128 * 2 + 0] = a0; red[g128 * 2 + 1] = a1; }
            __syncthreads();
            if (!kh) {
                int q = g128 >> 5, u = g128 & 31;
                gsm[(0 * 4 + q) * 32 + u] = a0 + red[g128 * 2 + 0] + gba;
                gsm[(1 * 4 + q) * 32 + u] = a1 + red[g128 * 2 + 1] + gbb;
            }
            __syncthreads();
        }

        if (tid < 64) {
            float iv = gsm[(b2 * 4 + 0) * 32 + uu];
            float fv = gsm[(b2 * 4 + 1) * 32 + uu];
            float gv = gsm[(b2 * 4 + 2) * 32 + uu];
            float ov = gsm[(b2 * 4 + 3) * 32 + uu];
            float c2 = sigf(fv) * cB + sigf(iv) * tanhf(gv);
            float h2 = sigf(ov) * tanhf(c2);
            bool m = (tb < mylen);
            float hn = m ? h2 : hB;
            cB = m ? c2 : cB;
            hB = hn;
            if (!last)
                g_hx[((nxt * 2 + 1) * 16 + bg) * 512 + (b2 << 8) + (r << 5) + uu] = hn;
            Hout[((size_t)tb * BB + batch0 + b2) * 512 + 1 * 256 + (r << 5) + uu] =
                m ? h2 : 0.0f;
        }
        __syncthreads();
        if (!last && tid == 0) { __threadfence(); st_rel(flgB + r, s + 1); }
    }
}

// ---------------- emit transpose + mask output ----------------
__global__ void finalize_kernel(const float* __restrict__ emitb,
                                const int* __restrict__ sent,
                                float* __restrict__ out, int out_size) {
    int bid = blockIdx.x;            // b*256 + t
    int b = bid >> 8, t = bid & 255;
    int k = threadIdx.x;
    if (k < KK) out[(size_t)bid * KK + k] = emitb[((size_t)t * BB + b) * KK + k];
    if (k == KK) {
        int idx = MASK_OFF + bid;
        if (idx < out_size) out[idx] = (sent[bid] != 0) ? 1.0f : 0.0f;
    }
}

// ---------------- CRF ----------------
__global__ void crf_kernel(const float* __restrict__ emitb,
                           const int* __restrict__ tags,
                           const int* __restrict__ lengths,
                           const float* __restrict__ start_t,
                           const float* __restrict__ end_t,
                           const float* __restrict__ trans,
                           float* __restrict__ scratch) {
    int b = blockIdx.x;
    int tid = threadIdx.x;           // 64
    __shared__ float trs[KK * KK];
    __shared__ float score[KK];
    __shared__ float nsc[KK];
    __shared__ float rbuf[64];
    __shared__ float numsh;

    for (int i = tid; i < KK * KK; i += 64) trs[i] = trans[i];
    int len = lengths[b];
    __syncthreads();

    float part = 0.0f;
    for (int t = 1 + tid; t < len; t += 64) {
        int tg = tags[b * TT + t];
        int pg = tags[b * TT + t - 1];
        part += trs[pg * KK + tg] + emitb[((size_t)t * BB + b) * KK + tg];
    }
    rbuf[tid] = part;
    __syncthreads();
    for (int s = 32; s > 0; s >>= 1) {
        if (tid < s) rbuf[tid] += rbuf[tid + s];
        __syncthreads();
    }
    if (tid == 0) {
        int t0 = tags[b * TT + 0];
        numsh = rbuf[0] + start_t[t0] + emitb[(size_t)b * KK + t0]
              + end_t[tags[b * TT + len - 1]];
    }

    if (tid < KK) score[tid] = start_t[tid] + emitb[(size_t)b * KK + tid];
    __syncthreads();
    for (int t = 1; t < len; t++) {
        if (tid < KK) {
            int k = tid;
            float m = -1e30f;
#pragma unroll 4
            for (int j = 0; j < KK; j++) {
                float v = score[j] + trs[j * KK + k];
                m = fmaxf(m, v);
            }
            float ssum = 0.0f;
#pragma unroll 4
            for (int j = 0; j < KK; j++)
                ssum += expf(score[j] + trs[j * KK + k] - m);
            nsc[k] = m + logf(ssum) + emitb[((size_t)t * BB + b) * KK + k];
        }
        __syncthreads();
        if (tid < KK) score[tid] = nsc[tid];
        __syncthreads();
    }
    if (tid == 0) {
        float m = -1e30f;
        for (int k = 0; k < KK; k++) m = fmaxf(m, score[k] + end_t[k]);
        float ssum = 0.0f;
        for (int k = 0; k < KK; k++) ssum += expf(score[k] + end_t[k] - m);
        float den = m + logf(ssum);
        scratch[b] = numsh - den;
    }
}

__global__ void loss_kernel(const float* __restrict__ scratch,
                            float* __restrict__ out, int out_size) {
    if (threadIdx.x == 0 && LOSS_OFF < out_size) {
        float s = 0.0f;
        for (int b = 0; b < BB; b++) s += scratch[b];
        out[LOSS_OFF] = s / (float)BB;
    }
}

// ---------------- launch ----------------
extern "C" void kernel_launch(void* const* d_in, const int* in_sizes, int n_in,
                              void* d_out, int out_size) {
    const int*   sentence = (const int*)d_in[0];
    const int*   lengths  = (const int*)d_in[1];
    const int*   tags     = (const int*)d_in[2];
    const float* embed    = (const float*)d_in[3];
    const float* Wih0f = (const float*)d_in[4];
    const float* Whh0f = (const float*)d_in[5];
    const float* b0f   = (const float*)d_in[6];
    const float* Wih0b = (const float*)d_in[7];
    const float* Whh0b = (const float*)d_in[8];
    const float* b0b   = (const float*)d_in[9];
    const float* Wih1f = (const float*)d_in[10];
    const float* Whh1f = (const float*)d_in[11];
    const float* b1f   = (const float*)d_in[12];
    const float* Wih1b = (const float*)d_in[13];
    const float* Whh1b = (const float*)d_in[14];
    const float* b1b   = (const float*)d_in[15];
    const float* Wout  = (const float*)d_in[16];
    const float* bout  = (const float*)d_in[17];
    const float* start_t = (const float*)d_in[18];
    const float* end_t   = (const float*)d_in[19];
    const float* trans   = (const float*)d_in[20];
    float* out = (float*)d_out;

    float *x0, *gxf, *gxb, *h1, *h2, *emitb, *scr;
    cudaGetSymbolAddress((void**)&x0, g_x0);
    cudaGetSymbolAddress((void**)&gxf, g_gxf);
    cudaGetSymbolAddress((void**)&gxb, g_gxb);
    cudaGetSymbolAddress((void**)&h1, g_h1);
    cudaGetSymbolAddress((void**)&h2, g_h2);
    cudaGetSymbolAddress((void**)&emitb, g_emit);
    cudaGetSymbolAddress((void**)&scr, g_scr);

    cudaFuncSetAttribute(lstm_layer, cudaFuncAttributeMaxDynamicSharedMemorySize,
                         LSTM_SMEM_BYTES);
    cudaFuncSetAttribute(mma_gemm, cudaFuncAttributeMaxDynamicSharedMemorySize,
                         MG_TOTAL);

    embed_kernel<<<ROWS_TB, 256>>>(sentence, embed, x0);

    // layer 0
    mma_gemm<<<dim3(16, 64, 2), 256, MG_TOTAL>>>(
        x0, Wih0f, Wih0b, b0f, b0b, gxf, gxb, 256, GATES);
    lstm_reset<<<128, 256>>>();
    lstm_layer<<<128, 256, LSTM_SMEM_BYTES>>>(gxf, gxb, Whh0f, Whh0b, lengths, h1);

    // layer 1
    mma_gemm<<<dim3(16, 64, 2), 256, MG_TOTAL>>>(
        h1, Wih1f, Wih1b, b1f, b1b, gxf, gxb, 512, GATES);
    lstm_reset<<<128, 256>>>();
    lstm_layer<<<128, 256, LSTM_SMEM_BYTES>>>(gxf, gxb, Whh1f, Whh1b, lengths, h2);

    // emissions
    mma_gemm<<<dim3(1, 64, 1), 256, MG_TOTAL>>>(
        h2, Wout, Wout, bout, bout, emitb, emitb, 512, KK);

    finalize_kernel<<<BB * TT, 64>>>(emitb, sentence, out, out_size);
    crf_kernel<<<BB, 64>>>(emitb, tags, lengths, start_t, end_t, trans, scr);
    loss_kernel<<<1, 32>>>(scr, out, out_size);
}